// round 13
// baseline (speedup 1.0000x reference)
#include <cuda_runtime.h>
#include <cuda_bf16.h>

#define NN 50000
#define KK 17
#define DIN 128
#define DOUT 64

// Scratch for projected features xp = x @ W : [N, 64] fp32 = 12.8 MB (fits in L2)
__device__ float g_xp[(size_t)NN * DOUT];

// ---------------------------------------------------------------------------
// Kernel 1: xp = x @ W (fp32). R4 version — at the scalar-FFMA roof (~21.3us).
// ---------------------------------------------------------------------------
__global__ void __launch_bounds__(256) gemm_kernel(
    const float* __restrict__ x, const float* __restrict__ wm)
{
    __shared__ float xs[128][32];
    __shared__ float ws[32][64];

    const int tid  = threadIdx.x;
    const int row0 = blockIdx.x * 128;
    const int c0   = (tid & 15) * 4;
    const int r0   = (tid >> 4) * 8;

    float acc[8][4];
#pragma unroll
    for (int i = 0; i < 8; i++)
#pragma unroll
        for (int j = 0; j < 4; j++) acc[i][j] = 0.f;

    for (int k0 = 0; k0 < DIN; k0 += 32) {
#pragma unroll
        for (int i = 0; i < 4; i++) {
            const int f4 = tid + 256 * i;
            const int r  = f4 >> 3;
            const int cc = (f4 & 7) * 4;
            int gr = row0 + r;
            if (gr > NN - 1) gr = NN - 1;
            const float4 v = *(const float4*)(x + (size_t)gr * DIN + k0 + cc);
            *(float4*)&xs[r][cc] = v;
        }
#pragma unroll
        for (int i = 0; i < 2; i++) {
            const int f4 = tid + 256 * i;
            const int r  = f4 >> 4;
            const int cc = (f4 & 15) * 4;
            const float4 v = *(const float4*)(wm + (size_t)(k0 + r) * DOUT + cc);
            *(float4*)&ws[r][cc] = v;
        }
        __syncthreads();

#pragma unroll
        for (int kk = 0; kk < 32; kk += 2) {
            const float4 w0 = *(const float4*)&ws[kk][c0];
            const float4 w1 = *(const float4*)&ws[kk + 1][c0];
#pragma unroll
            for (int i = 0; i < 8; i++) {
                const float2 xv = *(const float2*)&xs[r0 + i][kk];
                acc[i][0] += xv.x * w0.x;
                acc[i][1] += xv.x * w0.y;
                acc[i][2] += xv.x * w0.z;
                acc[i][3] += xv.x * w0.w;
                acc[i][0] += xv.y * w1.x;
                acc[i][1] += xv.y * w1.y;
                acc[i][2] += xv.y * w1.z;
                acc[i][3] += xv.y * w1.w;
            }
        }
        __syncthreads();
    }

#pragma unroll
    for (int i = 0; i < 8; i++) {
        const int gr = row0 + r0 + i;
        if (gr < NN) {
            float4 v;
            v.x = acc[i][0]; v.y = acc[i][1]; v.z = acc[i][2]; v.w = acc[i][3];
            *(float4*)&g_xp[(size_t)gr * DOUT + c0] = v;
        }
    }
}

// ---------------------------------------------------------------------------
// Kernel 2: weighted per-dim median, TWO nodes per thread, networks
// interleaved for 2-way ILP. Keys: value with low-5 mantissa bits replaced
// by element index. Sort: Green's 60-CE 16-sorter + Batcher (16,1)-merge
// tail (22 CEs, depth 5 — replaces the depth-16 serial insertion to cut
// exposed RAW latency at occ~58%). 82 CEs total, 2 FMNMX each, bit-exact.
// Indexed smem weight recovery; cumsum walk for the half-total crossing.
// ---------------------------------------------------------------------------
#define CE2(A, B) do {                         \
    const float a0_ = kA##A, b0_ = kA##B;      \
    const float a1_ = kB##A, b1_ = kB##B;      \
    kA##A = fminf(a0_, b0_);                   \
    kB##A = fminf(a1_, b1_);                   \
    kA##B = fmaxf(a0_, b0_);                   \
    kB##B = fmaxf(a1_, b1_);                   \
} while (0)

__global__ void __launch_bounds__(256) median_kernel(
    const int*   __restrict__ col,
    const float* __restrict__ ew,
    const float* __restrict__ bias,
    float*       __restrict__ out)
{
    __shared__ float swt[8][KK];
    __shared__ int   soff[8][KK];

    const int tid   = threadIdx.x;
    const int local = tid >> 6;            // 0..3 node-pairs per block
    const int d     = tid & 63;
    const int slotA = local * 2;
    const int slotB = slotA + 1;
    const int nodeA = (blockIdx.x * 4 + local) * 2;
    const int nodeB = nodeA + 1;

    if (d < 2 * KK) {
        const int which = (d >= KK);
        const int j     = which ? d - KK : d;
        const int slot  = slotA + which;
        const int nd    = nodeA + which;
        swt[slot][j]  = ew[nd * KK + j];
        soff[slot][j] = col[nd * KK + j] * DOUT;
    }
    __syncthreads();

    const float* __restrict__ xpd = g_xp + d;

    // load both nodes' values, embed index into low 5 mantissa bits
#define LOADJ(J)                                                               \
    float kA##J = __uint_as_float(                                             \
        (__float_as_uint(__ldg(xpd + soff[slotA][J])) & 0xFFFFFFE0u) |         \
        (unsigned)J);                                                          \
    float kB##J = __uint_as_float(                                             \
        (__float_as_uint(__ldg(xpd + soff[slotB][J])) & 0xFFFFFFE0u) |         \
        (unsigned)J);
    LOADJ(0)  LOADJ(1)  LOADJ(2)  LOADJ(3)  LOADJ(4)  LOADJ(5)
    LOADJ(6)  LOADJ(7)  LOADJ(8)  LOADJ(9)  LOADJ(10) LOADJ(11)
    LOADJ(12) LOADJ(13) LOADJ(14) LOADJ(15) LOADJ(16)
#undef LOADJ

    const float* wlA = swt[slotA];
    const float* wlB = swt[slotB];
    const float totA =
        ((wlA[0] + wlA[1]) + (wlA[2] + wlA[3])) +
        ((wlA[4] + wlA[5]) + (wlA[6] + wlA[7])) +
        ((wlA[8] + wlA[9]) + (wlA[10] + wlA[11])) +
        ((wlA[12] + wlA[13]) + (wlA[14] + wlA[15])) + wlA[16];
    const float totB =
        ((wlB[0] + wlB[1]) + (wlB[2] + wlB[3])) +
        ((wlB[4] + wlB[5]) + (wlB[6] + wlB[7])) +
        ((wlB[8] + wlB[9]) + (wlB[10] + wlB[11])) +
        ((wlB[12] + wlB[13]) + (wlB[14] + wlB[15])) + wlB[16];
    const float hfA = 0.5f * totA;
    const float hfB = 0.5f * totB;

    // --- Green's 16-element 60-CE sorting network on wires 0..15 (x2 ILP) ---
    CE2(0,1);  CE2(2,3);  CE2(4,5);  CE2(6,7);
    CE2(8,9);  CE2(10,11); CE2(12,13); CE2(14,15);

    CE2(0,2);  CE2(1,3);  CE2(4,6);  CE2(5,7);
    CE2(8,10); CE2(9,11); CE2(12,14); CE2(13,15);

    CE2(0,4);  CE2(1,5);  CE2(2,6);  CE2(3,7);
    CE2(8,12); CE2(9,13); CE2(10,14); CE2(11,15);

    CE2(0,8);  CE2(1,9);  CE2(2,10); CE2(3,11);
    CE2(4,12); CE2(5,13); CE2(6,14); CE2(7,15);

    CE2(5,10); CE2(6,9);  CE2(3,12); CE2(13,14);
    CE2(7,11); CE2(1,2);  CE2(4,8);

    CE2(1,4);  CE2(7,13); CE2(2,8);  CE2(11,14);

    CE2(2,4);  CE2(5,6);  CE2(9,10); CE2(11,13);

    CE2(3,8);  CE2(7,12);

    CE2(6,8);  CE2(10,12); CE2(3,5); CE2(7,9);

    CE2(3,4);  CE2(5,6);  CE2(7,8);  CE2(9,10); CE2(11,12);

    CE2(6,7);  CE2(8,9);

    // --- Batcher (16,1) merge tail: insert wire 16, depth 5, 22 CEs ---
    // k=16
    CE2(0,16);
    // k=8
    CE2(8,16);
    // k=4
    CE2(4,8);  CE2(5,9);  CE2(6,10); CE2(7,11); CE2(12,16);
    // k=2
    CE2(2,4);  CE2(3,5);  CE2(6,8);  CE2(7,9);
    CE2(10,12); CE2(11,13); CE2(14,16);
    // k=1
    CE2(1,2);  CE2(3,4);  CE2(5,6);  CE2(7,8);
    CE2(9,10); CE2(11,12); CE2(13,14); CE2(15,16);

    // --- recover sorted weights by embedded index (indexed LDS) ---
#define SWJ(J)                                                     \
    const float swA##J = wlA[__float_as_uint(kA##J) & 31u];        \
    const float swB##J = wlB[__float_as_uint(kB##J) & 31u];
    SWJ(0)  SWJ(1)  SWJ(2)  SWJ(3)  SWJ(4)  SWJ(5)  SWJ(6)  SWJ(7)  SWJ(8)
    SWJ(9)  SWJ(10) SWJ(11) SWJ(12) SWJ(13) SWJ(14) SWJ(15) SWJ(16)
#undef SWJ

    // --- cumsum walk (interleaved): first element with cumulative >= hf ---
    float cumA = swA0, cumB = swB0;
    float medA = kA0,  medB = kB0;
#define STEP(J)                                    \
    medA = (cumA < hfA) ? kA##J : medA;            \
    medB = (cumB < hfB) ? kB##J : medB;            \
    cumA += swA##J;                                \
    cumB += swB##J;
    STEP(1)  STEP(2)  STEP(3)  STEP(4)  STEP(5)  STEP(6)  STEP(7)  STEP(8)
    STEP(9)  STEP(10) STEP(11) STEP(12) STEP(13) STEP(14) STEP(15) STEP(16)
#undef STEP

    const float medvA = __uint_as_float(__float_as_uint(medA) & 0xFFFFFFE0u);
    const float medvB = __uint_as_float(__float_as_uint(medB) & 0xFFFFFFE0u);

    const float b = __ldg(&bias[d]);
    out[(size_t)nodeA * DOUT + d] = totA * medvA + b;
    out[(size_t)nodeB * DOUT + d] = totB * medvB + b;
}

// ---------------------------------------------------------------------------
// Inputs: x[N,128] f32, edge_index[2,E] i32, edge_weight[E] f32,
//         weight[128,64] f32, bias[64] f32. Output: [N,64] f32.
// ---------------------------------------------------------------------------
extern "C" void kernel_launch(void* const* d_in, const int* in_sizes, int n_in,
                              void* d_out, int out_size)
{
    const float* x    = (const float*)d_in[0];
    const int*   ei   = (const int*)  d_in[1];
    const float* ew   = (const float*)d_in[2];
    const float* wm   = (const float*)d_in[3];
    const float* bias = (const float*)d_in[4];
    float*       out  = (float*)d_out;

    const int E = in_sizes[1] / 2;
    const int* col = ei + E;

    gemm_kernel<<<(NN + 127) / 128, 256>>>(x, wm);
    median_kernel<<<NN / 8, 256>>>(col, ew, bias, out);   // 8 nodes per block
}

// round 14
// speedup vs baseline: 1.0561x; 1.0561x over previous
#include <cuda_runtime.h>
#include <cuda_bf16.h>

#define NN 50000
#define KK 17
#define DIN 128
#define DOUT 64

// Scratch for projected features xp = x @ W : [N, 64] fp32 = 12.8 MB (fits in L2)
__device__ float g_xp[(size_t)NN * DOUT];

// ---------------------------------------------------------------------------
// Kernel 1: xp = x @ W (fp32). R4 version — at the scalar-FFMA roof (~21.3us).
// ---------------------------------------------------------------------------
__global__ void __launch_bounds__(256) gemm_kernel(
    const float* __restrict__ x, const float* __restrict__ wm)
{
    __shared__ float xs[128][32];
    __shared__ float ws[32][64];

    const int tid  = threadIdx.x;
    const int row0 = blockIdx.x * 128;
    const int c0   = (tid & 15) * 4;
    const int r0   = (tid >> 4) * 8;

    float acc[8][4];
#pragma unroll
    for (int i = 0; i < 8; i++)
#pragma unroll
        for (int j = 0; j < 4; j++) acc[i][j] = 0.f;

    for (int k0 = 0; k0 < DIN; k0 += 32) {
#pragma unroll
        for (int i = 0; i < 4; i++) {
            const int f4 = tid + 256 * i;
            const int r  = f4 >> 3;
            const int cc = (f4 & 7) * 4;
            int gr = row0 + r;
            if (gr > NN - 1) gr = NN - 1;
            const float4 v = *(const float4*)(x + (size_t)gr * DIN + k0 + cc);
            *(float4*)&xs[r][cc] = v;
        }
#pragma unroll
        for (int i = 0; i < 2; i++) {
            const int f4 = tid + 256 * i;
            const int r  = f4 >> 4;
            const int cc = (f4 & 15) * 4;
            const float4 v = *(const float4*)(wm + (size_t)(k0 + r) * DOUT + cc);
            *(float4*)&ws[r][cc] = v;
        }
        __syncthreads();

#pragma unroll
        for (int kk = 0; kk < 32; kk += 2) {
            const float4 w0 = *(const float4*)&ws[kk][c0];
            const float4 w1 = *(const float4*)&ws[kk + 1][c0];
#pragma unroll
            for (int i = 0; i < 8; i++) {
                const float2 xv = *(const float2*)&xs[r0 + i][kk];
                acc[i][0] += xv.x * w0.x;
                acc[i][1] += xv.x * w0.y;
                acc[i][2] += xv.x * w0.z;
                acc[i][3] += xv.x * w0.w;
                acc[i][0] += xv.y * w1.x;
                acc[i][1] += xv.y * w1.y;
                acc[i][2] += xv.y * w1.z;
                acc[i][3] += xv.y * w1.w;
            }
        }
        __syncthreads();
    }

#pragma unroll
    for (int i = 0; i < 8; i++) {
        const int gr = row0 + r0 + i;
        if (gr < NN) {
            float4 v;
            v.x = acc[i][0]; v.y = acc[i][1]; v.z = acc[i][2]; v.w = acc[i][3];
            *(float4*)&g_xp[(size_t)gr * DOUT + c0] = v;
        }
    }
}

// ---------------------------------------------------------------------------
// Kernel 2: weighted per-dim median. Each thread handles dims (d, d+32) of
// ONE node -> the soff LDS, total-weight sum, hf, and wl pointer are shared
// between the two interleaved sorting networks (2-way ILP retained, ~half
// the LDS traffic of the 2-node version).
// Keys: value with low-5 mantissa bits replaced by element index. Sort via
// Green's 60-CE 16-sorter + 16-CE serial insertion (76 CEs, 2 FMNMX each,
// bit-exact -> index rides along). Indexed smem weight recovery; cumsum walk.
// ---------------------------------------------------------------------------
#define CE2(A, B) do {                         \
    const float a0_ = kA##A, b0_ = kA##B;      \
    const float a1_ = kB##A, b1_ = kB##B;      \
    kA##A = fminf(a0_, b0_);                   \
    kB##A = fminf(a1_, b1_);                   \
    kA##B = fmaxf(a0_, b0_);                   \
    kB##B = fmaxf(a1_, b1_);                   \
} while (0)

__global__ void __launch_bounds__(256) median_kernel(
    const int*   __restrict__ col,
    const float* __restrict__ ew,
    const float* __restrict__ bias,
    float*       __restrict__ out)
{
    __shared__ float swt[8][KK];
    __shared__ int   soff[8][KK];

    const int tid  = threadIdx.x;
    const int nl   = tid >> 5;          // node within block (0..7)
    const int d0   = tid & 31;          // first dim; second is d0+32
    const int node = blockIdx.x * 8 + nl;

    if (d0 < KK) {
        swt[nl][d0]  = ew[node * KK + d0];
        soff[nl][d0] = col[node * KK + d0] * DOUT;
    }
    __syncthreads();

    const float* __restrict__ xpd = g_xp + d0;

    // load both dims' values (shared row offset; +32 folds into LDG offset),
    // embed element index into low 5 mantissa bits
#define LOADJ(J)                                                               \
    const float* p##J = xpd + soff[nl][J];                                     \
    float kA##J = __uint_as_float(                                             \
        (__float_as_uint(__ldg(p##J)) & 0xFFFFFFE0u) | (unsigned)J);           \
    float kB##J = __uint_as_float(                                             \
        (__float_as_uint(__ldg(p##J + 32)) & 0xFFFFFFE0u) | (unsigned)J);
    LOADJ(0)  LOADJ(1)  LOADJ(2)  LOADJ(3)  LOADJ(4)  LOADJ(5)
    LOADJ(6)  LOADJ(7)  LOADJ(8)  LOADJ(9)  LOADJ(10) LOADJ(11)
    LOADJ(12) LOADJ(13) LOADJ(14) LOADJ(15) LOADJ(16)
#undef LOADJ

    const float* wl = swt[nl];
    const float total =
        ((wl[0] + wl[1]) + (wl[2] + wl[3])) + ((wl[4] + wl[5]) + (wl[6] + wl[7])) +
        ((wl[8] + wl[9]) + (wl[10] + wl[11])) +
        ((wl[12] + wl[13]) + (wl[14] + wl[15])) + wl[16];
    const float hf = 0.5f * total;

    // --- Green's 16-element 60-CE sorting network on wires 0..15 (x2 ILP) ---
    CE2(0,1);  CE2(2,3);  CE2(4,5);  CE2(6,7);
    CE2(8,9);  CE2(10,11); CE2(12,13); CE2(14,15);

    CE2(0,2);  CE2(1,3);  CE2(4,6);  CE2(5,7);
    CE2(8,10); CE2(9,11); CE2(12,14); CE2(13,15);

    CE2(0,4);  CE2(1,5);  CE2(2,6);  CE2(3,7);
    CE2(8,12); CE2(9,13); CE2(10,14); CE2(11,15);

    CE2(0,8);  CE2(1,9);  CE2(2,10); CE2(3,11);
    CE2(4,12); CE2(5,13); CE2(6,14); CE2(7,15);

    CE2(5,10); CE2(6,9);  CE2(3,12); CE2(13,14);
    CE2(7,11); CE2(1,2);  CE2(4,8);

    CE2(1,4);  CE2(7,13); CE2(2,8);  CE2(11,14);

    CE2(2,4);  CE2(5,6);  CE2(9,10); CE2(11,13);

    CE2(3,8);  CE2(7,12);

    CE2(6,8);  CE2(10,12); CE2(3,5); CE2(7,9);

    CE2(3,4);  CE2(5,6);  CE2(7,8);  CE2(9,10); CE2(11,12);

    CE2(6,7);  CE2(8,9);

    // --- serial insertion of element 16 (two chains interleave for ILP) ---
    CE2(15,16); CE2(14,15); CE2(13,14); CE2(12,13);
    CE2(11,12); CE2(10,11); CE2(9,10);  CE2(8,9);
    CE2(7,8);   CE2(6,7);   CE2(5,6);   CE2(4,5);
    CE2(3,4);   CE2(2,3);   CE2(1,2);   CE2(0,1);

    // --- recover sorted weights by embedded index (indexed LDS, shared wl) ---
#define SWJ(J)                                                     \
    const float swA##J = wl[__float_as_uint(kA##J) & 31u];         \
    const float swB##J = wl[__float_as_uint(kB##J) & 31u];
    SWJ(0)  SWJ(1)  SWJ(2)  SWJ(3)  SWJ(4)  SWJ(5)  SWJ(6)  SWJ(7)  SWJ(8)
    SWJ(9)  SWJ(10) SWJ(11) SWJ(12) SWJ(13) SWJ(14) SWJ(15) SWJ(16)
#undef SWJ

    // --- cumsum walk (interleaved, shared hf) ---
    float cumA = swA0, cumB = swB0;
    float medA = kA0,  medB = kB0;
#define STEP(J)                                   \
    medA = (cumA < hf) ? kA##J : medA;            \
    medB = (cumB < hf) ? kB##J : medB;            \
    cumA += swA##J;                               \
    cumB += swB##J;
    STEP(1)  STEP(2)  STEP(3)  STEP(4)  STEP(5)  STEP(6)  STEP(7)  STEP(8)
    STEP(9)  STEP(10) STEP(11) STEP(12) STEP(13) STEP(14) STEP(15) STEP(16)
#undef STEP

    const float medvA = __uint_as_float(__float_as_uint(medA) & 0xFFFFFFE0u);
    const float medvB = __uint_as_float(__float_as_uint(medB) & 0xFFFFFFE0u);

    out[(size_t)node * DOUT + d0]      = total * medvA + __ldg(&bias[d0]);
    out[(size_t)node * DOUT + d0 + 32] = total * medvB + __ldg(&bias[d0 + 32]);
}

// ---------------------------------------------------------------------------
// Inputs: x[N,128] f32, edge_index[2,E] i32, edge_weight[E] f32,
//         weight[128,64] f32, bias[64] f32. Output: [N,64] f32.
// ---------------------------------------------------------------------------
extern "C" void kernel_launch(void* const* d_in, const int* in_sizes, int n_in,
                              void* d_out, int out_size)
{
    const float* x    = (const float*)d_in[0];
    const int*   ei   = (const int*)  d_in[1];
    const float* ew   = (const float*)d_in[2];
    const float* wm   = (const float*)d_in[3];
    const float* bias = (const float*)d_in[4];
    float*       out  = (float*)d_out;

    const int E = in_sizes[1] / 2;
    const int* col = ei + E;

    gemm_kernel<<<(NN + 127) / 128, 256>>>(x, wm);
    median_kernel<<<NN / 8, 256>>>(col, ew, bias, out);   // 8 nodes per block
}

// round 15
// speedup vs baseline: 1.0856x; 1.0279x over previous
#include <cuda_runtime.h>
#include <cuda_bf16.h>

#define NN 50000
#define KK 17
#define DIN 128
#define DOUT 64

// Scratch for projected features xp = x @ W : [N, 64] fp32 = 12.8 MB (fits in L2)
__device__ float g_xp[(size_t)NN * DOUT];

// ---------------------------------------------------------------------------
// Kernel 1: xp = x @ W (fp32). R4 version — at the scalar-FFMA roof (~21.3us).
// ---------------------------------------------------------------------------
__global__ void __launch_bounds__(256) gemm_kernel(
    const float* __restrict__ x, const float* __restrict__ wm)
{
    __shared__ float xs[128][32];
    __shared__ float ws[32][64];

    const int tid  = threadIdx.x;
    const int row0 = blockIdx.x * 128;
    const int c0   = (tid & 15) * 4;
    const int r0   = (tid >> 4) * 8;

    float acc[8][4];
#pragma unroll
    for (int i = 0; i < 8; i++)
#pragma unroll
        for (int j = 0; j < 4; j++) acc[i][j] = 0.f;

    for (int k0 = 0; k0 < DIN; k0 += 32) {
#pragma unroll
        for (int i = 0; i < 4; i++) {
            const int f4 = tid + 256 * i;
            const int r  = f4 >> 3;
            const int cc = (f4 & 7) * 4;
            int gr = row0 + r;
            if (gr > NN - 1) gr = NN - 1;
            const float4 v = *(const float4*)(x + (size_t)gr * DIN + k0 + cc);
            *(float4*)&xs[r][cc] = v;
        }
#pragma unroll
        for (int i = 0; i < 2; i++) {
            const int f4 = tid + 256 * i;
            const int r  = f4 >> 4;
            const int cc = (f4 & 15) * 4;
            const float4 v = *(const float4*)(wm + (size_t)(k0 + r) * DOUT + cc);
            *(float4*)&ws[r][cc] = v;
        }
        __syncthreads();

#pragma unroll
        for (int kk = 0; kk < 32; kk += 2) {
            const float4 w0 = *(const float4*)&ws[kk][c0];
            const float4 w1 = *(const float4*)&ws[kk + 1][c0];
#pragma unroll
            for (int i = 0; i < 8; i++) {
                const float2 xv = *(const float2*)&xs[r0 + i][kk];
                acc[i][0] += xv.x * w0.x;
                acc[i][1] += xv.x * w0.y;
                acc[i][2] += xv.x * w0.z;
                acc[i][3] += xv.x * w0.w;
                acc[i][0] += xv.y * w1.x;
                acc[i][1] += xv.y * w1.y;
                acc[i][2] += xv.y * w1.z;
                acc[i][3] += xv.y * w1.w;
            }
        }
        __syncthreads();
    }

#pragma unroll
    for (int i = 0; i < 8; i++) {
        const int gr = row0 + r0 + i;
        if (gr < NN) {
            float4 v;
            v.x = acc[i][0]; v.y = acc[i][1]; v.z = acc[i][2]; v.w = acc[i][3];
            *(float4*)&g_xp[(size_t)gr * DOUT + c0] = v;
        }
    }
}

// ---------------------------------------------------------------------------
// Kernel 2: weighted per-dim median, dims (d, d+32) of one node per thread
// (2-way ILP). Keys: low mantissa BYTE replaced by j<<2 via PRMT (1 alu;
// <=255-ulp perturbation). Sort: Green's 60-CE 16-sorter + 16-CE serial
// insertion, FMNMX only. Weight recovery: address = PRMT(smem_base, key)
// with 256B-aligned weight rows -> 1 PRMT + 1 LDS, no AND/IADD. Walk:
// all-fma-pipe — indicator ind=fma.rn.sat(cum,-2^40, hf*2^40) (exact 0/1 of
// cum<hf) and telescoped median med += ind*(k[j+1]-k[j]).
// ---------------------------------------------------------------------------
__device__ __forceinline__ float fmasat(float a, float b, float c) {
    float d;
    asm("fma.rn.sat.f32 %0, %1, %2, %3;" : "=f"(d) : "f"(a), "f"(b), "f"(c));
    return d;
}

#define CE2(A, B) do {                         \
    const float a0_ = kA##A, b0_ = kA##B;      \
    const float a1_ = kB##A, b1_ = kB##B;      \
    kA##A = fminf(a0_, b0_);                   \
    kB##A = fminf(a1_, b1_);                   \
    kA##B = fmaxf(a0_, b0_);                   \
    kB##B = fmaxf(a1_, b1_);                   \
} while (0)

__global__ void __launch_bounds__(256) median_kernel(
    const int*   __restrict__ col,
    const float* __restrict__ ew,
    const float* __restrict__ bias,
    float*       __restrict__ out)
{
    __shared__ __align__(256) float swt[8][64];   // 256B per node row
    __shared__ int soff[8][KK];

    const int tid  = threadIdx.x;
    const int nl   = tid >> 5;          // node within block (0..7)
    const int d0   = tid & 31;          // first dim; second is d0+32
    const int node = blockIdx.x * 8 + nl;

    if (d0 < KK) {
        swt[nl][d0]  = ew[node * KK + d0];
        soff[nl][d0] = col[node * KK + d0] * DOUT;
    }
    __syncthreads();

    const float* __restrict__ xpd = g_xp + d0;
    const unsigned sb = (unsigned)__cvta_generic_to_shared(&swt[nl][0]);

    // load both dims' values; embed j<<2 into the low mantissa byte (1 PRMT)
#define LOADJ(J)                                                               \
    const float* p##J = xpd + soff[nl][J];                                     \
    float kA##J = __uint_as_float(                                             \
        __byte_perm(__float_as_uint(__ldg(p##J)),      (J) << 2, 0x3214));     \
    float kB##J = __uint_as_float(                                             \
        __byte_perm(__float_as_uint(__ldg(p##J + 32)), (J) << 2, 0x3214));
    LOADJ(0)  LOADJ(1)  LOADJ(2)  LOADJ(3)  LOADJ(4)  LOADJ(5)
    LOADJ(6)  LOADJ(7)  LOADJ(8)  LOADJ(9)  LOADJ(10) LOADJ(11)
    LOADJ(12) LOADJ(13) LOADJ(14) LOADJ(15) LOADJ(16)
#undef LOADJ

    const float* wl = swt[nl];
    const float total =
        ((wl[0] + wl[1]) + (wl[2] + wl[3])) + ((wl[4] + wl[5]) + (wl[6] + wl[7])) +
        ((wl[8] + wl[9]) + (wl[10] + wl[11])) +
        ((wl[12] + wl[13]) + (wl[14] + wl[15])) + wl[16];
    // hfB = hf * 2^40 = total * 2^39 (exact power-of-2 scale)
    const float hfB = total * 549755813888.0f;

    // --- Green's 16-element 60-CE sorting network on wires 0..15 (x2 ILP) ---
    CE2(0,1);  CE2(2,3);  CE2(4,5);  CE2(6,7);
    CE2(8,9);  CE2(10,11); CE2(12,13); CE2(14,15);

    CE2(0,2);  CE2(1,3);  CE2(4,6);  CE2(5,7);
    CE2(8,10); CE2(9,11); CE2(12,14); CE2(13,15);

    CE2(0,4);  CE2(1,5);  CE2(2,6);  CE2(3,7);
    CE2(8,12); CE2(9,13); CE2(10,14); CE2(11,15);

    CE2(0,8);  CE2(1,9);  CE2(2,10); CE2(3,11);
    CE2(4,12); CE2(5,13); CE2(6,14); CE2(7,15);

    CE2(5,10); CE2(6,9);  CE2(3,12); CE2(13,14);
    CE2(7,11); CE2(1,2);  CE2(4,8);

    CE2(1,4);  CE2(7,13); CE2(2,8);  CE2(11,14);

    CE2(2,4);  CE2(5,6);  CE2(9,10); CE2(11,13);

    CE2(3,8);  CE2(7,12);

    CE2(6,8);  CE2(10,12); CE2(3,5); CE2(7,9);

    CE2(3,4);  CE2(5,6);  CE2(7,8);  CE2(9,10); CE2(11,12);

    CE2(6,7);  CE2(8,9);

    // --- serial insertion of element 16 (two chains interleave for ILP) ---
    CE2(15,16); CE2(14,15); CE2(13,14); CE2(12,13);
    CE2(11,12); CE2(10,11); CE2(9,10);  CE2(8,9);
    CE2(7,8);   CE2(6,7);   CE2(5,6);   CE2(4,5);
    CE2(3,4);   CE2(2,3);   CE2(1,2);   CE2(0,1);

    // --- recover sorted weights: addr = PRMT(base, key) (rows 256B-aligned) ---
#define SWJ(J)                                                                 \
    float swA##J, swB##J;                                                      \
    {                                                                          \
        const unsigned aA = __byte_perm(sb, __float_as_uint(kA##J), 0x3214);   \
        const unsigned aB = __byte_perm(sb, __float_as_uint(kB##J), 0x3214);   \
        asm("ld.shared.b32 %0, [%1];" : "=f"(swA##J) : "r"(aA));               \
        asm("ld.shared.b32 %0, [%1];" : "=f"(swB##J) : "r"(aB));               \
    }
    SWJ(0)  SWJ(1)  SWJ(2)  SWJ(3)  SWJ(4)  SWJ(5)  SWJ(6)  SWJ(7)  SWJ(8)
    SWJ(9)  SWJ(10) SWJ(11) SWJ(12) SWJ(13) SWJ(14) SWJ(15) SWJ(16)
#undef SWJ

    // --- all-fma walk: ind = exact [cum < hf]; med telescopes to k_c ---
    float cumA = swA0, cumB = swB0;
    float medA = kA0,  medB = kB0;
#define STEP(J, JN) {                                         \
    const float iA = fmasat(cumA, -1099511627776.0f, hfB);    \
    const float iB = fmasat(cumB, -1099511627776.0f, hfB);    \
    medA = __fmaf_rn(iA, kA##JN - kA##J, medA);               \
    medB = __fmaf_rn(iB, kB##JN - kB##J, medB);               \
    cumA += swA##JN;                                          \
    cumB += swB##JN; }
    STEP(0,1)   STEP(1,2)   STEP(2,3)   STEP(3,4)
    STEP(4,5)   STEP(5,6)   STEP(6,7)   STEP(7,8)
    STEP(8,9)   STEP(9,10)  STEP(10,11) STEP(11,12)
    STEP(12,13) STEP(13,14) STEP(14,15) STEP(15,16)
#undef STEP

    out[(size_t)node * DOUT + d0]      = total * medA + __ldg(&bias[d0]);
    out[(size_t)node * DOUT + d0 + 32] = total * medB + __ldg(&bias[d0 + 32]);
}

// ---------------------------------------------------------------------------
// Inputs: x[N,128] f32, edge_index[2,E] i32, edge_weight[E] f32,
//         weight[128,64] f32, bias[64] f32. Output: [N,64] f32.
// ---------------------------------------------------------------------------
extern "C" void kernel_launch(void* const* d_in, const int* in_sizes, int n_in,
                              void* d_out, int out_size)
{
    const float* x    = (const float*)d_in[0];
    const int*   ei   = (const int*)  d_in[1];
    const float* ew   = (const float*)d_in[2];
    const float* wm   = (const float*)d_in[3];
    const float* bias = (const float*)d_in[4];
    float*       out  = (float*)d_out;

    const int E = in_sizes[1] / 2;
    const int* col = ei + E;

    gemm_kernel<<<(NN + 127) / 128, 256>>>(x, wm);
    median_kernel<<<NN / 8, 256>>>(col, ew, bias, out);   // 8 nodes per block
}